// round 12
// baseline (speedup 1.0000x reference)
#include <cuda_runtime.h>
#include <cstdint>

// Problem constants (match reference)
#define N_EVENTS   16
#define N_SAMPLES  32768
#define STEP_SIZE  256
#define BATCH      64

// out[b,j] = sum_e (j >= 256*idx[b,e]) ? x[b,e, j - 256*idx[b,e]] : 0
// Pure gather: ~67.6 MB compulsory reads + 8.4 MB writes, HBM-bound.
// Measured floor so far: 10.72 us = ~7.1 TB/s achieved (88% of spec).
//
// This variant: 8 samples per thread as TWO ADJACENT float4 groups
// (j and j+4*THREADS within the same 2048-sample CTA tile).
//  - 1024 CTAs total -> fits in ONE resident wave (capacity ~1184), so all
//    loads for the whole problem are in flight concurrently.
//  - One index load + one predicate serves 32 bytes of traffic (halved
//    issue-side overhead); 32 independent LDG.128 per thread.
//  - Per event each CTA reads ONE contiguous 8KB region (unlike the failed
//    mirrored variant which split into distant halves).
#define THREADS    256
#define SAMPLES_PER_BLOCK (THREADS * 8)          // 2048
#define CHUNKS     (N_SAMPLES / SAMPLES_PER_BLOCK)  // 16

__global__ __launch_bounds__(THREADS)
void render_gather_kernel(const float* __restrict__ x,
                          const int* __restrict__ indices,
                          float* __restrict__ out) {
    const int b = blockIdx.y;
    const int base = blockIdx.x * SAMPLES_PER_BLOCK + threadIdx.x * 4;
    const int j1 = base;                  // first float4 group
    const int j2 = base + THREADS * 4;    // second group, +1024 samples

    const int* idx_b = indices + b * N_EVENTS;
    const float* xb = x + (size_t)b * N_EVENTS * N_SAMPLES;

    float4 acc1 = make_float4(0.f, 0.f, 0.f, 0.f);
    float4 acc2 = make_float4(0.f, 0.f, 0.f, 0.f);

    #pragma unroll
    for (int e = 0; e < N_EVENTS; e++) {
        const int t = __ldg(idx_b + e) * STEP_SIZE;   // uniform across warp
        const float* xe = xb + (size_t)e * N_SAMPLES;
        const int k1 = j1 - t;
        const int k2 = j2 - t;
        // t multiple of 256, j multiple of 4 -> k multiple of 4 (16B aligned).
        // k < N_SAMPLES always holds since j < N_SAMPLES and t >= 0.
        if (k1 >= 0) {
            const float4 v = *reinterpret_cast<const float4*>(xe + k1);
            acc1.x += v.x; acc1.y += v.y; acc1.z += v.z; acc1.w += v.w;
        }
        if (k2 >= 0) {
            const float4 v = *reinterpret_cast<const float4*>(xe + k2);
            acc2.x += v.x; acc2.y += v.y; acc2.z += v.z; acc2.w += v.w;
        }
    }

    float* ob = out + (size_t)b * N_SAMPLES;
    *reinterpret_cast<float4*>(ob + j1) = acc1;
    *reinterpret_cast<float4*>(ob + j2) = acc2;
}

extern "C" void kernel_launch(void* const* d_in, const int* in_sizes, int n_in,
                              void* d_out, int out_size) {
    const float* x = (const float*)d_in[0];          // (64, 16, 32768) f32
    const int* indices = (const int*)d_in[1];        // (64, 16) int32
    float* out = (float*)d_out;                      // (64, 1, 32768) f32

    dim3 grid(CHUNKS, BATCH);                        // (16, 64) = 1024 CTAs
    render_gather_kernel<<<grid, THREADS>>>(x, indices, out);
}